// round 1
// baseline (speedup 1.0000x reference)
#include <cuda_runtime.h>
#include <math.h>

// ---------------- problem constants ----------------
#define BB   64
#define LL   1024          // 16*64 spatial positions
#define HH   256           // hidden
#define H2   512           // 2H
#define CC   111           // classes
#define TT   64            // time steps
#define CIN  1024
#define DD   256           // embedding dim
#define KCAT 879           // D + H + C  (GRU input) + H (hidden) = 623 + 256
#define KPAD 896           // KCAT padded to multiple of 112 (8 ksplits * 14 tiles * 8)
#define NGI  1024          // combined gate outputs: r(256) z(256) i_n(256) h_n(256)
#define KX   623           // D + H + C

// ---------------- device scratch ----------------
__device__ float g_featsT[(long)BB * H2 * LL];    // (B, 512, L)  134MB
__device__ float g_Wf[(long)BB * HH * LL];        // (B, 256, L)   67MB
__device__ float g_cov[BB * LL];
__device__ float g_h[BB * HH];
__device__ float g_context[BB * HH];
__device__ float g_gi[BB * NGI];
__device__ float g_xcat[BB * KPAD];
__device__ float g_WcatT[KPAD * NGI];             // transposed combined GRU weights
__device__ float g_gbias[NGI];
__device__ float g_outwT[KX * CC];                // transposed output weights

__device__ __forceinline__ float ftanh(float x) {
    float y; asm("tanh.approx.f32 %0, %1;" : "=f"(y) : "f"(x)); return y;
}

// ---------------- prep: transposes / zeros ----------------
__global__ void prep_kernel(const float* __restrict__ wih, const float* __restrict__ whh,
                            const float* __restrict__ bih, const float* __restrict__ bhh,
                            const float* __restrict__ outw) {
    const long R1 = (long)KPAD * NGI;
    const long TOTAL = R1 + NGI + (long)KX * CC + BB * HH + BB * LL + BB * HH + BB * KPAD;
    for (long idx = (long)blockIdx.x * blockDim.x + threadIdx.x; idx < TOTAL;
         idx += (long)gridDim.x * blockDim.x) {
        long i = idx;
        if (i < R1) {  // WcatT[k][j]
            int k = (int)(i >> 10), j = (int)(i & 1023);
            float v = 0.f;
            if (k < KCAT) {
                if (j < 768) {
                    if (k < KX) v = wih[j * KX + k];
                    else if (j < 512) v = whh[j * HH + (k - KX)];
                } else {
                    int jj = j - 768 + 512;  // h_n rows of Whh
                    if (k >= KX) v = whh[jj * HH + (k - KX)];
                }
            }
            g_WcatT[i] = v; continue;
        }
        i -= R1;
        if (i < NGI) {
            int j = (int)i;
            g_gbias[j] = (j < 512) ? bih[j] + bhh[j] : (j < 768) ? bih[j] : bhh[j - 256];
            continue;
        }
        i -= NGI;
        if (i < (long)KX * CC) { int k = (int)(i / CC), c = (int)(i % CC);
            g_outwT[i] = outw[c * KX + k]; continue; }
        i -= (long)KX * CC;
        if (i < BB * HH) { g_h[i] = 0.f; continue; } i -= BB * HH;
        if (i < BB * LL) { g_cov[i] = 0.f; continue; } i -= BB * LL;
        if (i < BB * HH) { g_context[i] = 0.f; continue; } i -= BB * HH;
        g_xcat[i] = 0.f;
    }
}

// ---------------- batched SGEMM: C[b] = A @ B[b] (+bias, +posenc) ----------------
// A: (M,K) row-major shared across batch. B: (K,N) row-major per batch. C: (M,N).
// mode 0: add conv_b[m] + positional_encoding(l=n, o=m).  mode 1: add bias[m].
__global__ __launch_bounds__(256) void sgemm_kernel(
    const float* __restrict__ A, const float* __restrict__ Bg, float* __restrict__ Cg,
    int M, int N, int K, const float* __restrict__ bias, int mode) {
    const int bx = blockIdx.x, by = blockIdx.y, b = blockIdx.z;
    const float* Bp = Bg + (long)b * K * N;
    float* Cp = Cg + (long)b * M * N;
    const int tid = threadIdx.x;
    __shared__ float As[8][128];
    __shared__ float Bs[8][128];
    float acc[8][8];
#pragma unroll
    for (int i = 0; i < 8; i++)
#pragma unroll
        for (int j = 0; j < 8; j++) acc[i][j] = 0.f;

    const int m0 = by * 128, n0 = bx * 128;
    const int arow = tid >> 1, acol = (tid & 1) * 4;
    const int brow = tid >> 5, bcol = (tid & 31) * 4;
    const int ty = tid >> 4, tx = tid & 15;

    for (int k0 = 0; k0 < K; k0 += 8) {
        float4 a4 = *(const float4*)&A[(long)(m0 + arow) * K + k0 + acol];
        As[acol + 0][arow] = a4.x; As[acol + 1][arow] = a4.y;
        As[acol + 2][arow] = a4.z; As[acol + 3][arow] = a4.w;
        *(float4*)&Bs[brow][bcol] = *(const float4*)&Bp[(long)(k0 + brow) * N + n0 + bcol];
        __syncthreads();
#pragma unroll
        for (int kk = 0; kk < 8; kk++) {
            float ra[8], rb[8];
#pragma unroll
            for (int i = 0; i < 8; i++) ra[i] = As[kk][ty * 8 + i];
#pragma unroll
            for (int j = 0; j < 8; j++) rb[j] = Bs[kk][tx * 8 + j];
#pragma unroll
            for (int i = 0; i < 8; i++)
#pragma unroll
                for (int j = 0; j < 8; j++) acc[i][j] = fmaf(ra[i], rb[j], acc[i][j]);
        }
        __syncthreads();
    }
#pragma unroll
    for (int i = 0; i < 8; i++) {
        int m = m0 + ty * 8 + i;
        float bia = bias[m];
        float freq = 0.f;
        if (mode == 0) freq = expf(-(float)(m & ~1) * (9.210340371976184f / 512.f));
#pragma unroll
        for (int j = 0; j < 8; j++) {
            int n = n0 + tx * 8 + j;
            float v = acc[i][j] + bia;
            if (mode == 0) {
                float ang = (float)n * freq;
                v += (m & 1) ? cosf(ang) : sinf(ang);
            }
            Cp[(long)m * N + n] = v;
        }
    }
}

// ---------------- per-step fused kernel ----------------
// Phase1 (t>0): GRU gates from g_gi -> h_t; output logits for step t-1.
// (t==TT: phase1 only.)  Phase2: attention scores+softmax+coverage+context.
// Phase3: build xcat_t, init g_gi with bias.
__global__ __launch_bounds__(256) void step_kernel(
    int t,
    const float* __restrict__ count, const int* __restrict__ target,
    const float* __restrict__ emb,
    const float* __restrict__ attn_v, const float* __restrict__ attn_vb,
    const float* __restrict__ cov_w, const float* __restrict__ cov_b,
    const float* __restrict__ out_b, float* __restrict__ d_out) {
    const int b = blockIdx.x, tid = threadIdx.x;
    __shared__ float s_hc[HH], s_cw[HH], s_cb[HH], s_v[HH];
    __shared__ float s_ctx[HH];
    __shared__ float s_alpha[LL];
    __shared__ float s_x2[640];
    __shared__ float s_red[8];

    // -------- phase 1: finalize h_t from gi(t-1), emit out_{t-1} --------
    if (t > 0) {
        const int i = tid;  // 256 threads == H
        const float* gi = g_gi + b * NGI;
        float gr = gi[i], gz = gi[256 + i], gin = gi[512 + i], ghn = gi[768 + i];
        float hold = g_h[b * HH + i];
        float r = 1.f / (1.f + expf(-gr));
        float z = 1.f / (1.f + expf(-gz));
        float n = tanhf(gin + r * ghn);
        float hn = (1.f - z) * n + z * hold;
        g_h[b * HH + i] = hn;
        s_x2[i] = hn;
        s_x2[256 + i] = g_context[b * HH + i];   // context_{t-1} (not yet overwritten)
        if (i < CC) s_x2[512 + i] = count[b * CC + i];
        __syncthreads();
        if (tid < CC) {
            float acc = out_b[tid];
#pragma unroll 4
            for (int k = 0; k < KX; k++) acc = fmaf(g_outwT[k * CC + tid], s_x2[k], acc);
            d_out[((long)b * TT + (t - 1)) * CC + tid] = acc;
        }
        if (t == TT) return;
        __syncthreads();
    }

    // -------- phase 2: attention --------
    {
        const int i = tid;
        s_hc[i] = g_h[b * HH + i];   // h_t (zeros at t==0 from prep)
        s_cw[i] = cov_w[i];
        s_cb[i] = cov_b[i];
        s_v[i]  = attn_v[i];
    }
    __syncthreads();

    float4 covv = *(const float4*)&g_cov[b * LL + tid * 4];
    const float vb = attn_vb[0];
    float a0 = vb, a1 = vb, a2 = vb, a3 = vb;
    const float4* wfp = (const float4*)(g_Wf + (long)b * HH * LL) + tid;
#pragma unroll 4
    for (int h = 0; h < HH; h++) {
        float4 wf = wfp[h * (LL / 4)];
        float base = s_cb[h] + s_hc[h];
        float cw = s_cw[h], vv = s_v[h];
        a0 = fmaf(vv, ftanh(fmaf(covv.x, cw, wf.x + base)), a0);
        a1 = fmaf(vv, ftanh(fmaf(covv.y, cw, wf.y + base)), a1);
        a2 = fmaf(vv, ftanh(fmaf(covv.z, cw, wf.z + base)), a2);
        a3 = fmaf(vv, ftanh(fmaf(covv.w, cw, wf.w + base)), a3);
    }
    // block softmax over 1024 logits (256 threads x 4)
    const int warp = tid >> 5, lane = tid & 31;
    float mx = fmaxf(fmaxf(a0, a1), fmaxf(a2, a3));
#pragma unroll
    for (int o = 16; o > 0; o >>= 1) mx = fmaxf(mx, __shfl_xor_sync(0xffffffffu, mx, o));
    if (lane == 0) s_red[warp] = mx;
    __syncthreads();
    float M = s_red[0];
#pragma unroll
    for (int w = 1; w < 8; w++) M = fmaxf(M, s_red[w]);
    float e0 = __expf(a0 - M), e1 = __expf(a1 - M), e2 = __expf(a2 - M), e3 = __expf(a3 - M);
    float sm = e0 + e1 + e2 + e3;
#pragma unroll
    for (int o = 16; o > 0; o >>= 1) sm += __shfl_xor_sync(0xffffffffu, sm, o);
    __syncthreads();                       // protect s_red reuse
    if (lane == 0) s_red[warp] = sm;
    __syncthreads();
    float S = 0.f;
#pragma unroll
    for (int w = 0; w < 8; w++) S += s_red[w];
    float inv = 1.f / S;
    float al0 = e0 * inv, al1 = e1 * inv, al2 = e2 * inv, al3 = e3 * inv;
    *(float4*)&s_alpha[tid * 4] = make_float4(al0, al1, al2, al3);
    covv.x += al0; covv.y += al1; covv.z += al2; covv.w += al3;
    *(float4*)&g_cov[b * LL + tid * 4] = covv;
    __syncthreads();

    // context[d] = sum_l alpha[l] * featsT[b, d, l],  d < 256
    const float4* ftp = (const float4*)(g_featsT + (long)b * H2 * LL);
    for (int dd = 0; dd < 32; dd++) {
        int d = warp * 32 + dd;
        float sum = 0.f;
#pragma unroll
        for (int k = 0; k < 8; k++) {
            float4 f  = ftp[(long)d * (LL / 4) + k * 32 + lane];
            float4 al = *(const float4*)&s_alpha[(k * 32 + lane) * 4];
            sum = fmaf(f.x, al.x, sum); sum = fmaf(f.y, al.y, sum);
            sum = fmaf(f.z, al.z, sum); sum = fmaf(f.w, al.w, sum);
        }
#pragma unroll
        for (int o = 16; o > 0; o >>= 1) sum += __shfl_xor_sync(0xffffffffu, sum, o);
        if (lane == 0) { g_context[b * HH + d] = sum; s_ctx[d] = sum; }
    }
    __syncthreads();

    // -------- phase 3: xcat_t and gi bias init --------
    const int y = (t == 0) ? 1 : target[b * TT + (t - 1)];
    for (int idx = tid; idx < KCAT; idx += 256) {
        float v;
        if (idx < 256)      v = emb[y * DD + idx];
        else if (idx < 512) v = s_ctx[idx - 256];
        else if (idx < KX)  v = count[b * CC + (idx - 512)];
        else                v = s_hc[idx - KX];
        g_xcat[b * KPAD + idx] = v;
    }
    for (int j = tid; j < NGI; j += 256) g_gi[b * NGI + j] = g_gbias[j];
}

// ---------------- GRU gate GEMM: gi(64x1024) += xcat(64x896) @ WcatT(896x1024) ----------------
// grid = 16 N-tiles * 8 K-splits = 128 blocks; 64x64 tile, K-chunk 112, atomic accumulate.
__global__ __launch_bounds__(256) void gru_gemm_kernel() {
    const int nt = blockIdx.x & 15, ks = blockIdx.x >> 4;
    const int n0 = nt * 64, k0 = ks * 112;
    const int tid = threadIdx.x;
    __shared__ float Xs[8][64];
    __shared__ float Ws[8][64];
    const int ml = tid >> 2, kl = (tid & 3) * 2;
    const int kw = tid >> 5, nn = (tid & 31) * 2;
    const int ty = tid >> 4, tx = tid & 15;
    float acc[4][4];
#pragma unroll
    for (int i = 0; i < 4; i++)
#pragma unroll
        for (int j = 0; j < 4; j++) acc[i][j] = 0.f;

    for (int kt = 0; kt < 14; kt++) {
        const int k = k0 + kt * 8;
        Xs[kl + 0][ml] = g_xcat[ml * KPAD + k + kl + 0];
        Xs[kl + 1][ml] = g_xcat[ml * KPAD + k + kl + 1];
        float2 w2 = *(const float2*)&g_WcatT[(k + kw) * NGI + n0 + nn];
        Ws[kw][nn] = w2.x; Ws[kw][nn + 1] = w2.y;
        __syncthreads();
#pragma unroll
        for (int kk = 0; kk < 8; kk++) {
            float rx[4], rw[4];
#pragma unroll
            for (int i = 0; i < 4; i++) rx[i] = Xs[kk][ty * 4 + i];
#pragma unroll
            for (int j = 0; j < 4; j++) rw[j] = Ws[kk][tx * 4 + j];
#pragma unroll
            for (int i = 0; i < 4; i++)
#pragma unroll
                for (int j = 0; j < 4; j++) acc[i][j] = fmaf(rx[i], rw[j], acc[i][j]);
        }
        __syncthreads();
    }
#pragma unroll
    for (int i = 0; i < 4; i++)
#pragma unroll
        for (int j = 0; j < 4; j++)
            atomicAdd(&g_gi[(ty * 4 + i) * NGI + n0 + tx * 4 + j], acc[i][j]);
}

// ---------------- launch ----------------
extern "C" void kernel_launch(void* const* d_in, const int* in_sizes, int n_in,
                              void* d_out, int out_size) {
    const float* fm      = (const float*)d_in[0];
    const float* count   = (const float*)d_in[1];
    const int*   target  = (const int*)d_in[2];
    const float* conv_w  = (const float*)d_in[3];
    const float* conv_b  = (const float*)d_in[4];
    const float* emb     = (const float*)d_in[5];
    const float* gru_wih = (const float*)d_in[6];
    const float* gru_whh = (const float*)d_in[7];
    const float* gru_bih = (const float*)d_in[8];
    const float* gru_bhh = (const float*)d_in[9];
    const float* attn_w  = (const float*)d_in[10];
    const float* attn_b  = (const float*)d_in[11];
    const float* attn_v  = (const float*)d_in[12];
    const float* attn_vb = (const float*)d_in[13];
    const float* cov_w   = (const float*)d_in[14];
    const float* cov_b   = (const float*)d_in[15];
    const float* out_w   = (const float*)d_in[16];
    const float* out_b   = (const float*)d_in[17];
    float* out = (float*)d_out;

    prep_kernel<<<1024, 256>>>(gru_wih, gru_whh, gru_bih, gru_bhh, out_w);

    float* featsT; cudaGetSymbolAddress((void**)&featsT, g_featsT);
    float* Wf;     cudaGetSymbolAddress((void**)&Wf, g_Wf);

    // featsT[b] = conv_w(512x1024) @ fm[b](1024x1024) + conv_b + posenc
    sgemm_kernel<<<dim3(LL / 128, H2 / 128, BB), 256>>>(conv_w, fm, featsT,
                                                        H2, LL, CIN, conv_b, 0);
    // Wf[b] = attn_w(256x512) @ featsT[b](512x1024) + attn_b
    sgemm_kernel<<<dim3(LL / 128, HH / 128, BB), 256>>>(attn_w, featsT, Wf,
                                                        HH, LL, H2, attn_b, 1);
    for (int t = 0; t < TT; t++) {
        step_kernel<<<BB, 256>>>(t, count, target, emb, attn_v, attn_vb,
                                 cov_w, cov_b, out_b, out);
        gru_gemm_kernel<<<128, 256>>>();
    }
    // final gate update + out_{T-1}
    step_kernel<<<BB, 256>>>(TT, count, target, emb, attn_v, attn_vb,
                             cov_w, cov_b, out_b, out);
}

// round 2
// speedup vs baseline: 1.6344x; 1.6344x over previous
#include <cuda_runtime.h>
#include <math.h>

// ---------------- problem constants ----------------
#define BB   64
#define LL   1024          // 16*64 spatial positions
#define HH   256           // hidden
#define H2   512           // 2H
#define CC   111           // classes
#define TT   64            // time steps
#define CIN  1024
#define DD   256           // embedding dim
#define KCAT 879           // D + H + C + H
#define KPAD 896
#define NGI  1024          // gates: r z i_n h_n
#define KX   623           // D + H + C
#define NCH  4             // score chunks per batch (256 l each)

// ---------------- device scratch ----------------
__device__ float g_F[(long)BB * H2 * LL];   // rows 0-255: ctx feats, 256-511: Wf
__device__ float g_scores[BB * LL];
__device__ float g_cov[BB * LL];
__device__ float g_h[2 * BB * HH];          // double-buffered hidden
__device__ float g_context[BB * HH];
__device__ float g_gi[BB * NGI];
__device__ float g_xcat[BB * KPAD];
__device__ float g_WcatT[KPAD * NGI];
__device__ float g_gbias[NGI];
__device__ float g_outwT[KX * CC];
__device__ float g_W2[H2 * CIN];            // combined conv(top)/attn@conv(bottom)
__device__ float g_peB[H2 * LL];            // pe[l,o]+conv_b[o] as (o,l)
__device__ float g_E[H2 * LL];              // epilogue table for main GEMM

__device__ __forceinline__ float ftanh(float x) {
    float y; asm("tanh.approx.f32 %0, %1;" : "=f"(y) : "f"(x)); return y;
}
__device__ __forceinline__ float pe_val(int l, int o) {
    float f = expf((float)(o & ~1) * (-9.210340371976184f / 512.f));
    float a = (float)l * f;
    return (o & 1) ? cosf(a) : sinf(a);
}

// ---------------- prep ----------------
__global__ void prep_kernel(const float* __restrict__ wih, const float* __restrict__ whh,
                            const float* __restrict__ bih, const float* __restrict__ bhh,
                            const float* __restrict__ outw, const float* __restrict__ convw,
                            const float* __restrict__ convb) {
    const long R1 = (long)KPAD * NGI;                 // WcatT
    const long R2 = R1 + NGI;                         // gbias
    const long R3 = R2 + (long)KX * CC;               // outwT
    const long R4 = R3 + 256L * CIN;                  // W2 top
    const long R5 = R4 + (long)H2 * LL;               // peB
    const long R6 = R5 + 256L * LL;                   // E top
    const long ZTOT = 2L*BB*HH + BB*LL + BB*HH + BB*KPAD;
    const long TOTAL = R6 + ZTOT;
    for (long idx = (long)blockIdx.x * blockDim.x + threadIdx.x; idx < TOTAL;
         idx += (long)gridDim.x * blockDim.x) {
        long i = idx;
        if (i < R1) {
            int k = (int)(i >> 10), j = (int)(i & 1023);
            float v = 0.f;
            if (k < KCAT) {
                if (j < 768) {
                    if (k < KX) v = wih[j * KX + k];
                    else if (j < 512) v = whh[j * HH + (k - KX)];
                } else {
                    if (k >= KX) v = whh[(j - 768 + 512) * HH + (k - KX)];
                }
            }
            g_WcatT[i] = v; continue;
        }
        if (i < R2) { int j = (int)(i - R1);
            g_gbias[j] = (j < 512) ? bih[j] + bhh[j] : (j < 768) ? bih[j] : bhh[j - 256];
            continue; }
        if (i < R3) { long p = i - R2; int k = (int)(p / CC), c = (int)(p % CC);
            g_outwT[p] = outw[c * KX + k]; continue; }
        if (i < R4) { long p = i - R3; g_W2[p] = convw[p]; continue; }
        if (i < R5) { long p = i - R4; int o = (int)(p >> 10), l = (int)(p & 1023);
            g_peB[p] = pe_val(l, o) + convb[o]; continue; }
        if (i < R6) { long p = i - R5; int m = (int)(p >> 10), l = (int)(p & 1023);
            g_E[p] = convb[m] + pe_val(l, m); continue; }
        long p = i - R6;
        if (p < 2L*BB*HH) { g_h[p] = 0.f; continue; } p -= 2L*BB*HH;
        if (p < BB*LL) { g_cov[p] = 0.f; continue; } p -= BB*LL;
        if (p < BB*HH) { g_context[p] = 0.f; continue; } p -= BB*HH;
        g_xcat[p] = 0.f;
    }
}

// ---------------- batched SGEMM, double-buffered ----------------
// C[b](M,N) = A(M,K) @ B[b](K,N)  [+ bias[m]] [+ Etab[m,n]]
__global__ __launch_bounds__(256, 2) void sgemm_kernel(
    const float* __restrict__ A, const float* __restrict__ Bg, float* __restrict__ Cg,
    int M, int N, int K, const float* __restrict__ bias, const float* __restrict__ Etab) {
    const int bx = blockIdx.x, by = blockIdx.y, b = blockIdx.z;
    const float* Bp = Bg + (long)b * K * N;
    float* Cp = Cg + (long)b * M * N;
    const int tid = threadIdx.x;
    __shared__ float As[2][8][128];
    __shared__ float Bs[2][8][128];
    float acc[8][8];
#pragma unroll
    for (int i = 0; i < 8; i++)
#pragma unroll
        for (int j = 0; j < 8; j++) acc[i][j] = 0.f;

    const int m0 = by * 128, n0 = bx * 128;
    const int arow = tid >> 1, acol = (tid & 1) * 4;
    const int brow = tid >> 5, bcol = (tid & 31) * 4;
    const int ty = tid >> 4, tx = tid & 15;
    const int nk = K / 8;

    float4 a4 = *(const float4*)&A[(long)(m0 + arow) * K + acol];
    float4 b4 = *(const float4*)&Bp[(long)brow * N + n0 + bcol];
    As[0][acol + 0][arow] = a4.x; As[0][acol + 1][arow] = a4.y;
    As[0][acol + 2][arow] = a4.z; As[0][acol + 3][arow] = a4.w;
    *(float4*)&Bs[0][brow][bcol] = b4;
    __syncthreads();

    int buf = 0;
    for (int kt = 0; kt < nk; kt++) {
        float4 a4n, b4n;
        const bool more = (kt + 1 < nk);
        if (more) {
            int k0 = (kt + 1) * 8;
            a4n = *(const float4*)&A[(long)(m0 + arow) * K + k0 + acol];
            b4n = *(const float4*)&Bp[(long)(k0 + brow) * N + n0 + bcol];
        }
#pragma unroll
        for (int kk = 0; kk < 8; kk++) {
            float ra[8], rb[8];
#pragma unroll
            for (int i = 0; i < 8; i++) ra[i] = As[buf][kk][ty * 8 + i];
#pragma unroll
            for (int j = 0; j < 8; j++) rb[j] = Bs[buf][kk][tx * 8 + j];
#pragma unroll
            for (int i = 0; i < 8; i++)
#pragma unroll
                for (int j = 0; j < 8; j++) acc[i][j] = fmaf(ra[i], rb[j], acc[i][j]);
        }
        if (more) {
            As[buf ^ 1][acol + 0][arow] = a4n.x; As[buf ^ 1][acol + 1][arow] = a4n.y;
            As[buf ^ 1][acol + 2][arow] = a4n.z; As[buf ^ 1][acol + 3][arow] = a4n.w;
            *(float4*)&Bs[buf ^ 1][brow][bcol] = b4n;
        }
        __syncthreads();
        buf ^= 1;
    }
#pragma unroll
    for (int i = 0; i < 8; i++) {
        int m = m0 + ty * 8 + i;
        float bia = bias ? bias[m] : 0.f;
#pragma unroll
        for (int j = 0; j < 8; j++) {
            int n = n0 + tx * 8 + j;
            float v = acc[i][j] + bia;
            if (Etab) v += Etab[(long)m * N + n];
            Cp[(long)m * N + n] = v;
        }
    }
}

// ---------------- K1: gate finalize + out_{t-1} + attention scores ----------------
__global__ __launch_bounds__(256) void score_kernel(
    int t, int nch,
    const float* __restrict__ count,
    const float* __restrict__ attn_v, const float* __restrict__ attn_vb,
    const float* __restrict__ cov_w, const float* __restrict__ cov_b,
    const float* __restrict__ out_b, float* __restrict__ d_out) {
    const int b = blockIdx.y, cx = blockIdx.x, tid = threadIdx.x;
    __shared__ float s_h[HH];
    float hn = 0.f;
    if (t > 0) {
        const float* gi = g_gi + b * NGI;
        float gr = gi[tid], gz = gi[256 + tid], gin = gi[512 + tid], ghn = gi[768 + tid];
        float hold = g_h[((t - 1) & 1) * BB * HH + b * HH + tid];
        float r = 1.f / (1.f + expf(-gr));
        float z = 1.f / (1.f + expf(-gz));
        float n = tanhf(gin + r * ghn);
        hn = (1.f - z) * n + z * hold;
    }
    s_h[tid] = hn;
    __syncthreads();

    if (cx == nch) {  // aux block: write h_t, emit out_{t-1}
        __shared__ float s_x2[640];
        if (t > 0) {
            g_h[(t & 1) * BB * HH + b * HH + tid] = hn;
            s_x2[tid] = hn;
            s_x2[256 + tid] = g_context[b * HH + tid];
            if (tid < CC) s_x2[512 + tid] = count[b * CC + tid];
            __syncthreads();
            if (tid < CC) {
                float acc = out_b[tid];
#pragma unroll 4
                for (int k = 0; k < KX; k++) acc = fmaf(g_outwT[k * CC + tid], s_x2[k], acc);
                d_out[((long)b * TT + (t - 1)) * CC + tid] = acc;
            }
        }
        return;
    }

    __shared__ float s_base[HH], s_cw[HH], s_v[HH];
    s_base[tid] = cov_b[tid] + hn;
    s_cw[tid] = cov_w[tid];
    s_v[tid] = attn_v[tid];
    __syncthreads();

    const int l = cx * 256 + tid;
    const float cov = g_cov[b * LL + l];
    const float* wf = g_F + ((long)b * H2 + 256) * LL + l;
    float a = attn_vb[0];
#pragma unroll 8
    for (int h = 0; h < HH; h++)
        a = fmaf(s_v[h], ftanh(fmaf(cov, s_cw[h], wf[(long)h * LL] + s_base[h])), a);
    g_scores[b * LL + l] = a;
}

// ---------------- K2: softmax + coverage + context + xcat + gi init ----------------
__global__ __launch_bounds__(256) void ctx_kernel(
    int t, const float* __restrict__ count, const int* __restrict__ target,
    const float* __restrict__ emb) {
    const int b = blockIdx.y, c = blockIdx.x, tid = threadIdx.x;
    const int warp = tid >> 5, lane = tid & 31;
    __shared__ float s_alpha[LL];
    __shared__ float s_red[8];

    float4 sc = ((const float4*)(g_scores + b * LL))[tid];
    float mx = fmaxf(fmaxf(sc.x, sc.y), fmaxf(sc.z, sc.w));
#pragma unroll
    for (int o = 16; o > 0; o >>= 1) mx = fmaxf(mx, __shfl_xor_sync(0xffffffffu, mx, o));
    if (lane == 0) s_red[warp] = mx;
    __syncthreads();
    float M = s_red[0];
#pragma unroll
    for (int w = 1; w < 8; w++) M = fmaxf(M, s_red[w]);
    float e0 = __expf(sc.x - M), e1 = __expf(sc.y - M);
    float e2 = __expf(sc.z - M), e3 = __expf(sc.w - M);
    float sm = e0 + e1 + e2 + e3;
#pragma unroll
    for (int o = 16; o > 0; o >>= 1) sm += __shfl_xor_sync(0xffffffffu, sm, o);
    __syncthreads();
    if (lane == 0) s_red[warp] = sm;
    __syncthreads();
    float S = 0.f;
#pragma unroll
    for (int w = 0; w < 8; w++) S += s_red[w];
    float inv = 1.f / S;
    float4 al = make_float4(e0 * inv, e1 * inv, e2 * inv, e3 * inv);
    ((float4*)s_alpha)[tid] = al;
    if (c == 0) {
        float4 cv = ((float4*)(g_cov + b * LL))[tid];
        cv.x += al.x; cv.y += al.y; cv.z += al.z; cv.w += al.w;
        ((float4*)(g_cov + b * LL))[tid] = cv;
    }
    __syncthreads();

    // context rows d = c*32 .. c*32+31 (each warp does 4 rows)
    const float* fb = g_F + (long)b * H2 * LL;
#pragma unroll
    for (int r = 0; r < 4; r++) {
        int d = c * 32 + warp * 4 + r;
        const float4* row = (const float4*)(fb + (long)d * LL);
        float sum = 0.f;
#pragma unroll
        for (int it = 0; it < 8; it++) {
            float4 f = row[it * 32 + lane];
            float4 a4 = ((const float4*)s_alpha)[it * 32 + lane];
            sum = fmaf(f.x, a4.x, sum); sum = fmaf(f.y, a4.y, sum);
            sum = fmaf(f.z, a4.z, sum); sum = fmaf(f.w, a4.w, sum);
        }
#pragma unroll
        for (int o = 16; o > 0; o >>= 1) sum += __shfl_xor_sync(0xffffffffu, sum, o);
        if (lane == 0) {
            g_context[b * HH + d] = sum;
            g_xcat[b * KPAD + 256 + d] = sum;
        }
    }

    if (tid < 128) g_gi[b * NGI + c * 128 + tid] = g_gbias[c * 128 + tid];
    if (c == 1) {
        int y = (t == 0) ? 1 : target[b * TT + (t - 1)];
        g_xcat[b * KPAD + tid] = emb[y * DD + tid];
    }
    if (c == 2 && tid < CC) g_xcat[b * KPAD + 512 + tid] = count[b * CC + tid];
    if (c == 3) g_xcat[b * KPAD + KX + tid] = g_h[(t & 1) * BB * HH + b * HH + tid];
}

// ---------------- K3: GRU gate GEMM (K-split, atomic) ----------------
__global__ __launch_bounds__(256) void gru_gemm_kernel() {
    const int nt = blockIdx.x & 15, ks = blockIdx.x >> 4;
    const int n0 = nt * 64, k0 = ks * 112;
    const int tid = threadIdx.x;
    __shared__ float Xs[8][64];
    __shared__ float Ws[8][64];
    const int ml = tid >> 2, kl = (tid & 3) * 2;
    const int kw = tid >> 5, nn = (tid & 31) * 2;
    const int ty = tid >> 4, tx = tid & 15;
    float acc[4][4];
#pragma unroll
    for (int i = 0; i < 4; i++)
#pragma unroll
        for (int j = 0; j < 4; j++) acc[i][j] = 0.f;

    for (int kt = 0; kt < 14; kt++) {
        const int k = k0 + kt * 8;
        Xs[kl + 0][ml] = g_xcat[ml * KPAD + k + kl + 0];
        Xs[kl + 1][ml] = g_xcat[ml * KPAD + k + kl + 1];
        float2 w2 = *(const float2*)&g_WcatT[(k + kw) * NGI + n0 + nn];
        Ws[kw][nn] = w2.x; Ws[kw][nn + 1] = w2.y;
        __syncthreads();
#pragma unroll
        for (int kk = 0; kk < 8; kk++) {
            float rx[4], rw[4];
#pragma unroll
            for (int i = 0; i < 4; i++) rx[i] = Xs[kk][ty * 4 + i];
#pragma unroll
            for (int j = 0; j < 4; j++) rw[j] = Ws[kk][tx * 4 + j];
#pragma unroll
            for (int i = 0; i < 4; i++)
#pragma unroll
                for (int j = 0; j < 4; j++) acc[i][j] = fmaf(rx[i], rw[j], acc[i][j]);
        }
        __syncthreads();
    }
#pragma unroll
    for (int i = 0; i < 4; i++)
#pragma unroll
        for (int j = 0; j < 4; j++)
            atomicAdd(&g_gi[(ty * 4 + i) * NGI + n0 + tx * 4 + j], acc[i][j]);
}

// ---------------- launch ----------------
extern "C" void kernel_launch(void* const* d_in, const int* in_sizes, int n_in,
                              void* d_out, int out_size) {
    const float* fm      = (const float*)d_in[0];
    const float* count   = (const float*)d_in[1];
    const int*   target  = (const int*)d_in[2];
    const float* conv_w  = (const float*)d_in[3];
    const float* conv_b  = (const float*)d_in[4];
    const float* emb     = (const float*)d_in[5];
    const float* gru_wih = (const float*)d_in[6];
    const float* gru_whh = (const float*)d_in[7];
    const float* gru_bih = (const float*)d_in[8];
    const float* gru_bhh = (const float*)d_in[9];
    const float* attn_w  = (const float*)d_in[10];
    const float* attn_b  = (const float*)d_in[11];
    const float* attn_v  = (const float*)d_in[12];
    const float* attn_vb = (const float*)d_in[13];
    const float* cov_w   = (const float*)d_in[14];
    const float* cov_b   = (const float*)d_in[15];
    const float* out_w   = (const float*)d_in[16];
    const float* out_b   = (const float*)d_in[17];
    float* out = (float*)d_out;

    float *pF, *pW2, *pPeB, *pE;
    cudaGetSymbolAddress((void**)&pF, g_F);
    cudaGetSymbolAddress((void**)&pW2, g_W2);
    cudaGetSymbolAddress((void**)&pPeB, g_peB);
    cudaGetSymbolAddress((void**)&pE, g_E);

    prep_kernel<<<1024, 256>>>(gru_wih, gru_whh, gru_bih, gru_bhh, out_w, conv_w, conv_b);

    // W2 bottom half: attn_w(256x512) @ conv_w(512x1024)
    sgemm_kernel<<<dim3(8, 2, 1), 256>>>(attn_w, conv_w, pW2 + 256 * CIN,
                                         256, CIN, H2, nullptr, nullptr);
    // E bottom half: attn_w @ (pe+conv_b) + attn_b
    sgemm_kernel<<<dim3(8, 2, 1), 256>>>(attn_w, pPeB, pE + 256 * LL,
                                         256, LL, H2, attn_b, nullptr);
    // main: g_F[b] = W2 @ fm[b] + E   (rows 0-255 ctx feats, 256-511 Wf)
    sgemm_kernel<<<dim3(8, 4, BB), 256>>>(pW2, fm, pF,
                                          H2, LL, CIN, nullptr, pE);

    for (int t = 0; t < TT; t++) {
        score_kernel<<<dim3(NCH + 1, BB), 256>>>(t, NCH, count, attn_v, attn_vb,
                                                 cov_w, cov_b, out_b, out);
        ctx_kernel<<<dim3(8, BB), 256>>>(t, count, target, emb);
        gru_gemm_kernel<<<128, 256>>>();
    }
    score_kernel<<<dim3(1, BB), 256>>>(TT, 0, count, attn_v, attn_vb,
                                       cov_w, cov_b, out_b, out);
}